// round 13
// baseline (speedup 1.0000x reference)
#include <cuda_runtime.h>
#include <cuda_bf16.h>
#include <cuda_fp8.h>
#include <cstdint>

#define BHALF 4096
#define NROW  8192
#define DIM   256
#define INV_T (1.0f/0.07f)
#define LOG2E 1.4426950408889634f

#define TILE_M 128
#define STRIDE_B 272             // bytes: 256 + 16 pad -> conflict-free frag loads
#define TILE_BYTES (TILE_M * STRIDE_B)               // 34816
#define SMEM_BYTES (3 * TILE_BYTES)                  // A + 2x B = 104448

#define NTILE 64                 // 8192 / 128
#define NPAIR 2080               // upper-triangle tile count
#define NTHREADS 512             // 16 warps, 4x4 warp grid, 32x32 per warp

__device__ unsigned char g_zn[NROW * DIM];   // normalized rows, e4m3 (2 MB)
__device__ float g_sumexp[NROW];
__device__ float g_pos[NROW];
__device__ volatile unsigned g_gen;          // grid-barrier generation
__device__ unsigned g_count;                 // grid-barrier arrivals
__device__ unsigned g_done;                  // tail election

// ---------------------------------------------------------------------------
// soft grid barrier (single-wave persistent grid only)
// ---------------------------------------------------------------------------
__device__ __forceinline__ void grid_barrier(unsigned nblk) {
    __threadfence();
    __syncthreads();
    if (threadIdx.x == 0) {
        unsigned gen = g_gen;
        if (atomicAdd(&g_count, 1) == nblk - 1) {
            g_count = 0;
            __threadfence();
            g_gen = gen + 1;
        } else {
            while (g_gen == gen) {}
            __threadfence();
        }
    }
    __syncthreads();
}

// ---------------------------------------------------------------------------
// fast exp via 2^y on the FMA pipe
// ---------------------------------------------------------------------------
__device__ __forceinline__ float fast_exp2(float y) {
    float t  = y + 12582912.0f;          // round-to-nearest-int trick (1.5*2^23)
    int   i  = __float_as_int(t);
    float nf = t - 12582912.0f;
    float f  = y - nf;                   // f in [-0.5, 0.5]
    float p  = fmaf(1.3333558e-3f, f, 9.6181291e-3f);
    p = fmaf(p, f, 5.5504109e-2f);
    p = fmaf(p, f, 2.4022651e-1f);
    p = fmaf(p, f, 6.9314718e-1f);
    p = fmaf(p, f, 1.0f);
    return p * __int_as_float((i << 23) + 0x3F800000);
}

// fp8 e4m3 MMA, fp32 accumulate: m16n8k32
__device__ __forceinline__ void mma_fp8(float c[4],
                                        unsigned a0, unsigned a1, unsigned a2, unsigned a3,
                                        unsigned b0, unsigned b1) {
    asm volatile(
        "mma.sync.aligned.m16n8k32.row.col.f32.e4m3.e4m3.f32 "
        "{%0,%1,%2,%3}, {%4,%5,%6,%7}, {%8,%9}, {%0,%1,%2,%3};\n"
        : "+f"(c[0]), "+f"(c[1]), "+f"(c[2]), "+f"(c[3])
        : "r"(a0), "r"(a1), "r"(a2), "r"(a3), "r"(b0), "r"(b1));
}

__device__ __forceinline__ void cp_async16(void* smem_dst, const void* gsrc) {
    unsigned s = (unsigned)__cvta_generic_to_shared(smem_dst);
    asm volatile("cp.async.cg.shared.global [%0], [%1], 16;\n" :: "r"(s), "l"(gsrc));
}
__device__ __forceinline__ void cp_commit() {
    asm volatile("cp.async.commit_group;\n" ::: "memory");
}
__device__ __forceinline__ void cp_wait1() {
    asm volatile("cp.async.wait_group 1;\n" ::: "memory");
}
__device__ __forceinline__ void cp_wait0() {
    asm volatile("cp.async.wait_group 0;\n" ::: "memory");
}

__device__ __forceinline__ void load_tile_cp(char* dst, const unsigned char* src,
                                             int tid) {
    #pragma unroll
    for (int it = 0; it < 4; it++) {
        int idx = tid + it * NTHREADS;     // 2048 16B chunks
        int r = idx >> 4, c = idx & 15;
        cp_async16(dst + r * STRIDE_B + c * 16, src + r * 256 + c * 16);
    }
}

__device__ __forceinline__ void load_tile_sync(char* dst, const unsigned char* src,
                                               int tid) {
    const uint4* gsrc = (const uint4*)src;
    #pragma unroll
    for (int it = 0; it < 4; it++) {
        int idx = tid + it * NTHREADS;
        int r = idx >> 4, c = idx & 15;
        *(uint4*)(dst + r * STRIDE_B + c * 16) = gsrc[r * 16 + c];
    }
}

// decode linear upper-triangle tile index q -> (i, j)
__device__ __forceinline__ void decode_tile(int q, int& i, int& j) {
    i = 0;
    int rem = q;
    while (rem >= NTILE - i) { rem -= NTILE - i; i++; }
    j = i + rem;
}

__device__ __forceinline__ void flush_rsum(float (&rsum)[2][2], int iT,
                                           int wm, int g, int tig) {
    #pragma unroll
    for (int mt = 0; mt < 2; mt++)
        #pragma unroll
        for (int h = 0; h < 2; h++) {
            float v = rsum[mt][h];
            v += __shfl_xor_sync(0xffffffffu, v, 1);
            v += __shfl_xor_sync(0xffffffffu, v, 2);
            if (tig == 0)
                atomicAdd(&g_sumexp[iT * TILE_M + wm * 32 + mt * 16 + g + h * 8], v);
            rsum[mt][h] = 0.0f;
        }
}

__device__ __forceinline__ void flush_csum(float (&csum)[4][2], int jP,
                                           int wn, int g, int tig) {
    #pragma unroll
    for (int nt = 0; nt < 4; nt++)
        #pragma unroll
        for (int p = 0; p < 2; p++) {
            float v = csum[nt][p];
            v += __shfl_xor_sync(0xffffffffu, v, 4);
            v += __shfl_xor_sync(0xffffffffu, v, 8);
            v += __shfl_xor_sync(0xffffffffu, v, 16);
            if (g == 0)
                atomicAdd(&g_sumexp[jP * TILE_M + wn * 32 + nt * 8 + tig * 2 + p], v);
        }
}

// ---------------------------------------------------------------------------
// one-warp row normalize -> e4m3
// ---------------------------------------------------------------------------
__device__ __forceinline__ void norm_row(int row, const float* __restrict__ z_i,
                                         const float* __restrict__ z_j, int lane) {
    const float* src = (row < BHALF) ? (z_i + (size_t)row * DIM)
                                     : (z_j + (size_t)(row - BHALF) * DIM);
    float4 v0 = ((const float4*)src)[lane * 2];
    float4 v1 = ((const float4*)src)[lane * 2 + 1];
    float ss = v0.x*v0.x + v0.y*v0.y + v0.z*v0.z + v0.w*v0.w
             + v1.x*v1.x + v1.y*v1.y + v1.z*v1.z + v1.w*v1.w;
    #pragma unroll
    for (int o = 16; o; o >>= 1) ss += __shfl_xor_sync(0xffffffffu, ss, o);
    float inv = 1.0f / fmaxf(sqrtf(ss), 1e-8f);

    unsigned p0 = __nv_cvt_float2_to_fp8x2(make_float2(v0.x*inv, v0.y*inv),
                                           __NV_SATFINITE, __NV_E4M3);
    unsigned p1 = __nv_cvt_float2_to_fp8x2(make_float2(v0.z*inv, v0.w*inv),
                                           __NV_SATFINITE, __NV_E4M3);
    unsigned p2 = __nv_cvt_float2_to_fp8x2(make_float2(v1.x*inv, v1.y*inv),
                                           __NV_SATFINITE, __NV_E4M3);
    unsigned p3 = __nv_cvt_float2_to_fp8x2(make_float2(v1.z*inv, v1.w*inv),
                                           __NV_SATFINITE, __NV_E4M3);
    uint2 u;
    u.x = (p0 & 0xffffu) | (p1 << 16);
    u.y = (p2 & 0xffffu) | (p3 << 16);
    *(uint2*)(g_zn + (size_t)row * DIM + lane * 8) = u;
    if (lane == 0) { g_sumexp[row] = 0.0f; g_pos[row] = 0.0f; }
}

// ---------------------------------------------------------------------------
// fused persistent kernel: normalize -> grid barrier -> symmetric fp8 GEMM
// with fused softmax-sum epilogue -> last-block loss tail.
// 512 threads, 4x4 warp grid, 32x32 warp tile, m16n8k32 e4m3 (8 kk steps).
// ---------------------------------------------------------------------------
__global__ void __launch_bounds__(NTHREADS) ntxent_fused_kernel(
    const float* __restrict__ z_i, const float* __restrict__ z_j,
    float* __restrict__ out)
{
    extern __shared__ char smem[];
    char* As  = smem;
    char* Bs0 = smem + TILE_BYTES;
    char* Bs1 = Bs0 + TILE_BYTES;

    const int tid  = threadIdx.x;
    const int warp = tid >> 5, lane = tid & 31;
    const int g    = lane >> 2, tig = lane & 3;
    const int wm   = warp >> 2, wn = warp & 3;   // 4x4 grid -> 32x32 per warp
    const unsigned nblk = gridDim.x;

    // ---- phase 1: normalize ----
    {
        int stride = nblk * 16;
        for (int r0 = blockIdx.x * 16 + warp; r0 < NROW; r0 += 2 * stride) {
            int r1 = r0 + stride;
            norm_row(r0, z_i, z_j, lane);
            if (r1 < NROW) norm_row(r1, z_i, z_j, lane);
        }
    }

    grid_barrier(nblk);

    // ---- phase 2: GEMM over balanced contiguous triangle ranges ----
    int bid = blockIdx.x;
    int q0  = (int)(((long long)bid * NPAIR) / nblk);
    int q1  = (int)(((long long)(bid + 1) * NPAIR) / nblk);

    if (q0 < q1) {
        int iCur, jCur;
        decode_tile(q0, iCur, jCur);

        load_tile_sync(As, g_zn + (size_t)iCur * TILE_M * DIM, tid);
        int iLoaded = iCur;
        load_tile_cp(Bs0, g_zn + (size_t)jCur * TILE_M * DIM, tid);
        cp_commit();

        float rsum[2][2];
        rsum[0][0] = rsum[0][1] = rsum[1][0] = rsum[1][1] = 0.f;

        for (int q = q0; q < q1; q++) {
            int buf = (q - q0) & 1;
            int iN = iCur, jN = jCur + 1;
            if (jN == NTILE) { iN++; jN = iN; }

            __syncthreads();                    // prior tile fully consumed

            if (q + 1 < q1)
                load_tile_cp(buf ? Bs0 : Bs1, g_zn + (size_t)jN * TILE_M * DIM, tid);
            cp_commit();                        // uniform group count

            if (iCur != iLoaded) {
                flush_rsum(rsum, iLoaded, wm, g, tig);
                load_tile_sync(As, g_zn + (size_t)iCur * TILE_M * DIM, tid);
                iLoaded = iCur;
            }

            cp_wait1();
            __syncthreads();

            const char* Bb = buf ? Bs1 : Bs0;

            float acc[2][4][4];
            #pragma unroll
            for (int mt = 0; mt < 2; mt++)
                #pragma unroll
                for (int nt = 0; nt < 4; nt++)
                    #pragma unroll
                    for (int ci = 0; ci < 4; ci++) acc[mt][nt][ci] = 0.f;

            #pragma unroll
            for (int kk = 0; kk < 8; kk++) {
                const int k0 = kk * 32 + tig * 4;     // byte offset within row
                unsigned a[2][4], b[4][2];
                #pragma unroll
                for (int mt = 0; mt < 2; mt++) {
                    const char* ap = As + (wm * 32 + mt * 16 + g) * STRIDE_B + k0;
                    a[mt][0] = *(const unsigned*)(ap);
                    a[mt][1] = *(const unsigned*)(ap + 8 * STRIDE_B);
                    a[mt][2] = *(const unsigned*)(ap + 16);
                    a[mt][3] = *(const unsigned*)(ap + 8 * STRIDE_B + 16);
                }
                #pragma unroll
                for (int nt = 0; nt < 4; nt++) {
                    const char* bp = Bb + (wn * 32 + nt * 8 + g) * STRIDE_B + k0;
                    b[nt][0] = *(const unsigned*)(bp);
                    b[nt][1] = *(const unsigned*)(bp + 16);
                }
                #pragma unroll
                for (int mt = 0; mt < 2; mt++)
                    #pragma unroll
                    for (int nt = 0; nt < 4; nt++)
                        mma_fp8(acc[mt][nt], a[mt][0], a[mt][1], a[mt][2], a[mt][3],
                                b[nt][0], b[nt][1]);
            }

            // ---- fused epilogue ----
            const bool diag = (jCur == iCur);
            const bool pos  = (jCur == iCur + 32);
            float csum[4][2];
            #pragma unroll
            for (int nt = 0; nt < 4; nt++) { csum[nt][0] = 0.f; csum[nt][1] = 0.f; }

            #pragma unroll
            for (int mt = 0; mt < 2; mt++)
                #pragma unroll
                for (int nt = 0; nt < 4; nt++)
                    #pragma unroll
                    for (int ci = 0; ci < 4; ci++) {
                        float v = acc[mt][nt][ci];
                        float e = fast_exp2(v * (INV_T * LOG2E));
                        if (diag | pos) {
                            int row = iCur * TILE_M + wm * 32 + mt * 16 + g + (ci >> 1) * 8;
                            int col = jCur * TILE_M + wn * 32 + nt * 8 + tig * 2 + (ci & 1);
                            if (pos & (col == row + BHALF)) {
                                float pv = v * INV_T;
                                g_pos[row] = pv;
                                g_pos[col] = pv;
                            }
                            if (diag & (col == row)) e = 0.0f;
                        }
                        rsum[mt][ci >> 1] += e;
                        csum[nt][ci & 1]  += e;
                    }

            if (!diag) flush_csum(csum, jCur, wn, g, tig);

            iCur = iN; jCur = jN;
        }

        flush_rsum(rsum, iLoaded, wm, g, tig);
        cp_wait0();
    }

    // ---- phase 3: last block computes the loss ----
    __threadfence();
    __syncthreads();
    __shared__ unsigned amLast;
    if (tid == 0)
        amLast = (atomicAdd(&g_done, 1) == nblk - 1) ? 1u : 0u;
    __syncthreads();

    if (amLast) {
        __threadfence();
        float s = 0.0f;
        for (int k = tid; k < NROW; k += NTHREADS)
            s += logf(__ldcg(&g_sumexp[k])) - __ldcg(&g_pos[k]);
        #pragma unroll
        for (int o = 16; o; o >>= 1) s += __shfl_xor_sync(0xffffffffu, s, o);
        __shared__ float sw[16];
        if (lane == 0) sw[warp] = s;
        __syncthreads();
        if (tid == 0) {
            float v = 0.0f;
            #pragma unroll
            for (int w = 0; w < 16; w++) v += sw[w];
            out[0] = v / (float)NROW;
            g_done = 0;              // reset for next graph replay
        }
    }
}

extern "C" void kernel_launch(void* const* d_in, const int* in_sizes, int n_in,
                              void* d_out, int out_size) {
    const float* z_i = (const float*)d_in[0];
    const float* z_j = (const float*)d_in[1];
    float* out = (float*)d_out;

    int dev = 0, nsm = 148;
    cudaGetDevice(&dev);
    cudaDeviceGetAttribute(&nsm, cudaDevAttrMultiProcessorCount, dev);
    if (nsm < 1) nsm = 148;
    if (nsm > 512) nsm = 512;

    cudaFuncSetAttribute(ntxent_fused_kernel,
                         cudaFuncAttributeMaxDynamicSharedMemorySize, SMEM_BYTES);

    ntxent_fused_kernel<<<nsm, NTHREADS, SMEM_BYTES>>>(z_i, z_j, out);
}